// round 1
// baseline (speedup 1.0000x reference)
#include <cuda_runtime.h>
#include <math.h>

#define BB 4
#define CC 256
#define CI 128
#define NP 4096

typedef unsigned long long u64;

// Scratch (device globals: allocation-free rule)
__device__ float g_q[BB * NP * CI];  // theta(x)  : (b, n, o)
__device__ float g_k[BB * NP * CI];  // phi(x)    : (b, m, o)
__device__ float g_v[BB * NP * CI];  // g(x)      : (b, m, o)
__device__ float g_o[BB * NP * CI];  // attention out (b, n, o)

// ---------------- packed fp32x2 helpers (sm_100+) ----------------
__device__ __forceinline__ u64 pack2(float lo, float hi) {
    u64 r;
    asm("mov.b64 %0, {%1, %2};" : "=l"(r) : "f"(lo), "f"(hi));
    return r;
}
__device__ __forceinline__ float2 unpack2(u64 v) {
    float2 f;
    asm("mov.b64 {%0, %1}, %2;" : "=f"(f.x), "=f"(f.y) : "l"(v));
    return f;
}
__device__ __forceinline__ void ffma2(u64& d, u64 a, u64 b) {
    asm("fma.rn.f32x2 %0, %1, %2, %0;" : "+l"(d) : "l"(a), "l"(b));
}
__device__ __forceinline__ u64 fmul2(u64 a, u64 b) {
    u64 d;
    asm("mul.rn.f32x2 %0, %1, %2;" : "=l"(d) : "l"(a), "l"(b));
    return d;
}

// =================================================================
// Kernel 1: QKV projections.
// dst[b, n, o] = sum_c W[o,c] * x[b,c,n] + bias[o]
// Block tile: 128 outputs (o) x 128 pixels (n). 256 threads, micro 8x8.
// grid = (NP/128, BB, 3)   z: 0=theta->g_q, 1=phi->g_k, 2=g->g_v
// =================================================================
__global__ __launch_bounds__(256) void proj_kernel(
    const float* __restrict__ x,
    const float* __restrict__ tw, const float* __restrict__ tb,
    const float* __restrict__ pw, const float* __restrict__ pb,
    const float* __restrict__ gw, const float* __restrict__ gb)
{
    __shared__ float xs[16][132];  // [k][n]
    __shared__ float ws[16][132];  // [k][o]

    const int z  = blockIdx.z;
    const int b  = blockIdx.y;
    const int n0 = blockIdx.x * 128;
    const float* W  = (z == 0) ? tw : (z == 1) ? pw : gw;
    const float* bi = (z == 0) ? tb : (z == 1) ? pb : gb;
    float*      dst = (z == 0) ? g_q : (z == 1) ? g_k : g_v;

    const int t  = threadIdx.x;
    const int tx = t & 15, ty = t >> 4;

    // o = ty + 16*i (i<8), n = 8*tx + 2*j + {0,1} (j<4)
    u64 acc2[8][4];
#pragma unroll
    for (int i = 0; i < 8; i++)
#pragma unroll
        for (int j = 0; j < 4; j++) acc2[i][j] = 0ull;

    const float* xb = x + (size_t)b * CC * NP + n0;

    for (int c0 = 0; c0 < CC; c0 += 16) {
        {   // xs[k][nn]: coalesced float4 over n
            int k   = t >> 5;
            int nn4 = (t & 31) * 4;
            *(float4*)&xs[k][nn4]     = *(const float4*)&xb[(size_t)(c0 + k) * NP + nn4];
            *(float4*)&xs[k + 8][nn4] = *(const float4*)&xb[(size_t)(c0 + k + 8) * NP + nn4];
        }
        {   // ws[k][oo]: W row-major (o, C), contiguous over c
            int k = t & 15, oo = t >> 4;
#pragma unroll
            for (int p = 0; p < 8; p++)
                ws[k][oo + 16 * p] = W[(size_t)(oo + 16 * p) * CC + c0 + k];
        }
        __syncthreads();
#pragma unroll
        for (int k = 0; k < 16; k++) {
            float4 b0 = *(const float4*)&xs[k][8 * tx];
            float4 b1 = *(const float4*)&xs[k][8 * tx + 4];
            u64 bp[4];
            bp[0] = pack2(b0.x, b0.y); bp[1] = pack2(b0.z, b0.w);
            bp[2] = pack2(b1.x, b1.y); bp[3] = pack2(b1.z, b1.w);
#pragma unroll
            for (int i = 0; i < 8; i++) {
                float a  = ws[k][ty + 16 * i];
                u64   a2 = pack2(a, a);
#pragma unroll
                for (int j = 0; j < 4; j++) ffma2(acc2[i][j], a2, bp[j]);
            }
        }
        __syncthreads();
    }

#pragma unroll
    for (int i = 0; i < 8; i++) {
        int   o  = ty + 16 * i;
        float bv = bi[o];
#pragma unroll
        for (int j = 0; j < 4; j++) {
            float2 f = unpack2(acc2[i][j]);
            int    n = n0 + 8 * tx + 2 * j;
            dst[(size_t)(b * NP + n) * CI + o]     = f.x + bv;
            dst[(size_t)(b * NP + n + 1) * CI + o] = f.y + bv;
        }
    }
}

// =================================================================
// Kernel 2: fused flash attention (fp32).
// Per block: batch b, 64 query rows. Loop K/V in 64-row tiles:
//   S = Q K^T  -> online softmax -> O += P V
// Thread map (tx<16, ty<16): S rows r=ty+16i (i<4), S cols m=tx+16j (j<4)
//                            O rows r=ty+16i,       O cols d=8tx..8tx+7
// grid = (NP/64, BB), 256 threads, ~115 KB dynamic smem.
// =================================================================
#define QS 132
#define PS 65

__global__ __launch_bounds__(256) void attn_kernel()
{
    extern __shared__ float smem[];
    float* Qs = smem;             // [64][QS]  (r, k)
    float* Ks = Qs + 64 * QS;     // [64][QS]  (m, k)
    float* Vs = Ks + 64 * QS;     // [64][QS]  (m, d)
    float* Ps = Vs + 64 * QS;     // [64][PS]  (r, m)

    const int b    = blockIdx.y;
    const int row0 = blockIdx.x * 64;
    const int t    = threadIdx.x;
    const int tx   = t & 15, ty = t >> 4;

    const float* gq = g_q + (size_t)b * NP * CI;
    const float* gk = g_k + (size_t)b * NP * CI;
    const float* gv = g_v + (size_t)b * NP * CI;

    // load Q tile (64 x 128)
#pragma unroll
    for (int p = 0; p < 8; p++) {
        int idx = p * 256 + t;
        int r   = idx >> 5;
        int k4  = (idx & 31) * 4;
        *(float4*)&Qs[r * QS + k4] = *(const float4*)&gq[(size_t)(row0 + r) * CI + k4];
    }

    u64   o2[4][4];
    float mrun[4], lrun[4];
#pragma unroll
    for (int i = 0; i < 4; i++) {
        mrun[i] = -INFINITY;
        lrun[i] = 0.0f;
#pragma unroll
        for (int p = 0; p < 4; p++) o2[i][p] = 0ull;
    }

    for (int m0 = 0; m0 < NP; m0 += 64) {
        __syncthreads();  // prior PV done reading Ks/Vs/Ps
#pragma unroll
        for (int p = 0; p < 8; p++) {
            int idx = p * 256 + t;
            int r   = idx >> 5;
            int k4  = (idx & 31) * 4;
            *(float4*)&Ks[r * QS + k4] = *(const float4*)&gk[(size_t)(m0 + r) * CI + k4];
            *(float4*)&Vs[r * QS + k4] = *(const float4*)&gv[(size_t)(m0 + r) * CI + k4];
        }
        __syncthreads();

        // ---- S = Q K^T (pairs over k, folded after the loop) ----
        u64 s2[4][4];
#pragma unroll
        for (int i = 0; i < 4; i++)
#pragma unroll
            for (int j = 0; j < 4; j++) s2[i][j] = 0ull;

#pragma unroll 4
        for (int k = 0; k < CI; k += 4) {
            float4 a4[4], b4[4];
#pragma unroll
            for (int i = 0; i < 4; i++) a4[i] = *(const float4*)&Qs[(ty + 16 * i) * QS + k];
#pragma unroll
            for (int j = 0; j < 4; j++) b4[j] = *(const float4*)&Ks[(tx + 16 * j) * QS + k];
#pragma unroll
            for (int i = 0; i < 4; i++) {
                const u64* ap = (const u64*)&a4[i];
#pragma unroll
                for (int j = 0; j < 4; j++) {
                    const u64* bp = (const u64*)&b4[j];
                    ffma2(s2[i][j], ap[0], bp[0]);
                    ffma2(s2[i][j], ap[1], bp[1]);
                }
            }
        }

        // ---- online softmax (row state replicated across the 16 lanes of a row) ----
#pragma unroll
        for (int i = 0; i < 4; i++) {
            float s[4];
#pragma unroll
            for (int j = 0; j < 4; j++) {
                float2 f = unpack2(s2[i][j]);
                s[j] = f.x + f.y;
            }
            float tmax = fmaxf(fmaxf(s[0], s[1]), fmaxf(s[2], s[3]));
#pragma unroll
            for (int d = 1; d < 16; d <<= 1)
                tmax = fmaxf(tmax, __shfl_xor_sync(0xffffffffu, tmax, d));
            float mnew = fmaxf(mrun[i], tmax);
            float corr = __expf(mrun[i] - mnew);
            mrun[i] = mnew;

            float ssum = 0.0f;
#pragma unroll
            for (int j = 0; j < 4; j++) {
                float e = __expf(s[j] - mnew);
                Ps[(ty + 16 * i) * PS + tx + 16 * j] = e;
                ssum += e;
            }
#pragma unroll
            for (int d = 1; d < 16; d <<= 1)
                ssum += __shfl_xor_sync(0xffffffffu, ssum, d);
            lrun[i] = lrun[i] * corr + ssum;

            u64 c2 = pack2(corr, corr);
#pragma unroll
            for (int p = 0; p < 4; p++) o2[i][p] = fmul2(o2[i][p], c2);
        }
        __syncthreads();

        // ---- O += P V ----
#pragma unroll 8
        for (int m = 0; m < 64; m++) {
            float4 v0 = *(const float4*)&Vs[m * QS + 8 * tx];
            float4 v1 = *(const float4*)&Vs[m * QS + 8 * tx + 4];
            const u64* vp0 = (const u64*)&v0;
            const u64* vp1 = (const u64*)&v1;
#pragma unroll
            for (int i = 0; i < 4; i++) {
                float pv = Ps[(ty + 16 * i) * PS + m];
                u64   p2 = pack2(pv, pv);
                ffma2(o2[i][0], p2, vp0[0]);
                ffma2(o2[i][1], p2, vp0[1]);
                ffma2(o2[i][2], p2, vp1[0]);
                ffma2(o2[i][3], p2, vp1[1]);
            }
        }
    }

    // finalize: O /= l, store (b, n, o)
    float* go = g_o + (size_t)b * NP * CI;
#pragma unroll
    for (int i = 0; i < 4; i++) {
        float  inv = 1.0f / lrun[i];
        float2 f0 = unpack2(o2[i][0]);
        float2 f1 = unpack2(o2[i][1]);
        float2 f2 = unpack2(o2[i][2]);
        float2 f3 = unpack2(o2[i][3]);
        float4 w0 = make_float4(f0.x * inv, f0.y * inv, f1.x * inv, f1.y * inv);
        float4 w1 = make_float4(f2.x * inv, f2.y * inv, f3.x * inv, f3.y * inv);
        size_t base = (size_t)(row0 + ty + 16 * i) * CI + 8 * tx;
        *(float4*)&go[base]     = w0;
        *(float4*)&go[base + 4] = w1;
    }
}

// =================================================================
// Kernel 3: output projection + bias + residual.
// out[b,c,n] = sum_o w_w[c,o]*g_o[b,n,o] + w_b[c] + x[b,c,n]
// Block tile: 64 c x 128 n. grid = (NP/128, CC/64, BB)
// =================================================================
__global__ __launch_bounds__(256) void outproj_kernel(
    const float* __restrict__ x,
    const float* __restrict__ ww, const float* __restrict__ wb,
    float* __restrict__ out)
{
    __shared__ float os[16][132];  // [o-chunk][n]
    __shared__ float ws[16][68];   // [o-chunk][c]

    const int b  = blockIdx.z;
    const int c0 = blockIdx.y * 64;
    const int n0 = blockIdx.x * 128;
    const int t  = threadIdx.x, tx = t & 15, ty = t >> 4;

    // c = ty + 16*i (i<4), n = 8*tx + 2*j + {0,1} (j<4)
    u64 acc2[4][4];
#pragma unroll
    for (int i = 0; i < 4; i++)
#pragma unroll
        for (int j = 0; j < 4; j++) acc2[i][j] = 0ull;

    const float* ob = g_o + (size_t)b * NP * CI;

    for (int o0 = 0; o0 < CI; o0 += 16) {
        {   // os[k][nn] transposed from pixel-major g_o
            int k4 = (t & 3) * 4;
            int nn = t >> 2;
#pragma unroll
            for (int h = 0; h < 2; h++) {
                float4 v = *(const float4*)&ob[(size_t)(n0 + nn + 64 * h) * CI + o0 + k4];
                os[k4 + 0][nn + 64 * h] = v.x;
                os[k4 + 1][nn + 64 * h] = v.y;
                os[k4 + 2][nn + 64 * h] = v.z;
                os[k4 + 3][nn + 64 * h] = v.w;
            }
        }
        {   // ws[k][cc] from w_w (C, CI) row-major
            int k = t & 15, cc = t >> 4;
#pragma unroll
            for (int p = 0; p < 4; p++)
                ws[k][cc + 16 * p] = ww[(size_t)(c0 + cc + 16 * p) * CI + o0 + k];
        }
        __syncthreads();
#pragma unroll
        for (int k = 0; k < 16; k++) {
            float4 b0 = *(const float4*)&os[k][8 * tx];
            float4 b1 = *(const float4*)&os[k][8 * tx + 4];
            u64 bp[4];
            bp[0] = pack2(b0.x, b0.y); bp[1] = pack2(b0.z, b0.w);
            bp[2] = pack2(b1.x, b1.y); bp[3] = pack2(b1.z, b1.w);
#pragma unroll
            for (int i = 0; i < 4; i++) {
                float a  = ws[k][ty + 16 * i];
                u64   a2 = pack2(a, a);
#pragma unroll
                for (int j = 0; j < 4; j++) ffma2(acc2[i][j], a2, bp[j]);
            }
        }
        __syncthreads();
    }

#pragma unroll
    for (int i = 0; i < 4; i++) {
        int    c    = c0 + ty + 16 * i;
        float  bv   = wb[c];
        size_t base = ((size_t)b * CC + c) * NP + n0 + 8 * tx;
        float4 xv0  = *(const float4*)&x[base];
        float4 xv1  = *(const float4*)&x[base + 4];
        float2 f0 = unpack2(acc2[i][0]);
        float2 f1 = unpack2(acc2[i][1]);
        float2 f2 = unpack2(acc2[i][2]);
        float2 f3 = unpack2(acc2[i][3]);
        float4 r0 = make_float4(f0.x + bv + xv0.x, f0.y + bv + xv0.y,
                                f1.x + bv + xv0.z, f1.y + bv + xv0.w);
        float4 r1 = make_float4(f2.x + bv + xv1.x, f2.y + bv + xv1.y,
                                f3.x + bv + xv1.z, f3.y + bv + xv1.w);
        *(float4*)&out[base]     = r0;
        *(float4*)&out[base + 4] = r1;
    }
}

// =================================================================
extern "C" void kernel_launch(void* const* d_in, const int* in_sizes, int n_in,
                              void* d_out, int out_size)
{
    const float* x  = (const float*)d_in[0];
    const float* tw = (const float*)d_in[1];
    const float* tb = (const float*)d_in[2];
    const float* pw = (const float*)d_in[3];
    const float* pb = (const float*)d_in[4];
    const float* gw = (const float*)d_in[5];
    const float* gb = (const float*)d_in[6];
    const float* ww = (const float*)d_in[7];
    const float* wb = (const float*)d_in[8];
    float* out = (float*)d_out;

    const int smem_attn = (3 * 64 * QS + 64 * PS) * (int)sizeof(float);
    cudaFuncSetAttribute(attn_kernel, cudaFuncAttributeMaxDynamicSharedMemorySize, smem_attn);

    proj_kernel<<<dim3(NP / 128, BB, 3), 256>>>(x, tw, tb, pw, pb, gw, gb);
    attn_kernel<<<dim3(NP / 64, BB), 256, smem_attn>>>();
    outproj_kernel<<<dim3(NP / 128, CC / 64, BB), 256>>>(x, ww, wb, out);
}